// round 1
// baseline (speedup 1.0000x reference)
#include <cuda_runtime.h>
#include <cuda_bf16.h>
#include <cstdint>

#define N_IMG 64
#define IMG_ELEMS (3 * 512 * 512)          // 786432
#define TOTAL_ELEMS (N_IMG * IMG_ELEMS)    // 50331648
#define BINS 256
#define CHUNK 8192                          // elems per block
#define BPI (IMG_ELEMS / CHUNK)             // 96 blocks per image
#define NBLOCKS (TOTAL_ELEMS / CHUNK)       // 6144
#define NWARPS 8

// ---------------- device scratch (allocation-free rule: __device__ globals) ----
__device__ unsigned char g_idx[TOTAL_ELEMS];          // 48 MB bucket indices
__device__ unsigned int  g_minmax[2 * N_IMG];         // [0..63] enc(min), [64..127] enc(max)
__device__ int           g_hist[N_IMG * BINS];
__device__ float         g_lut[N_IMG * BINS];

// Order-preserving float<->uint encoding for atomicMin/Max on floats
__device__ __forceinline__ unsigned fenc(float f) {
    unsigned u = __float_as_uint(f);
    return (u & 0x80000000u) ? ~u : (u | 0x80000000u);
}
__device__ __forceinline__ float fdec(unsigned u) {
    u = (u & 0x80000000u) ? (u ^ 0x80000000u) : ~u;
    return __uint_as_float(u);
}

// ---------------- k0: reset scratch -------------------------------------------
__global__ void k_init() {
    int gt = blockIdx.x * 256 + threadIdx.x;     // 64*256 = 16384 = N_IMG*BINS
    g_hist[gt] = 0;
    if (gt < N_IMG) {
        g_minmax[gt] = 0xFFFFFFFFu;              // min slot
        g_minmax[N_IMG + gt] = 0u;               // max slot
    }
}

// ---------------- k1: per-image min/max ---------------------------------------
__global__ void __launch_bounds__(256) k_minmax(const float4* __restrict__ x) {
    int b = blockIdx.x, t = threadIdx.x;
    int img = b / BPI;
    int base4 = b * (CHUNK / 4);
    float mn = 3.4e38f, mx = -3.4e38f;
#pragma unroll
    for (int i = 0; i < 8; i++) {
        float4 v = x[base4 + i * 256 + t];
        mn = fminf(mn, fminf(fminf(v.x, v.y), fminf(v.z, v.w)));
        mx = fmaxf(mx, fmaxf(fmaxf(v.x, v.y), fmaxf(v.z, v.w)));
    }
#pragma unroll
    for (int o = 16; o > 0; o >>= 1) {
        mn = fminf(mn, __shfl_xor_sync(0xffffffffu, mn, o));
        mx = fmaxf(mx, __shfl_xor_sync(0xffffffffu, mx, o));
    }
    __shared__ float smn[NWARPS], smx[NWARPS];
    int w = t >> 5;
    if ((t & 31) == 0) { smn[w] = mn; smx[w] = mx; }
    __syncthreads();
    if (t == 0) {
#pragma unroll
        for (int i = 1; i < NWARPS; i++) {
            mn = fminf(mn, smn[i]);
            mx = fmaxf(mx, smx[i]);
        }
        atomicMin(&g_minmax[img], fenc(mn));
        atomicMax(&g_minmax[N_IMG + img], fenc(mx));
    }
}

// ---------------- k2: bucket indices + per-image histogram --------------------
__global__ void __launch_bounds__(256) k_hist(const float4* __restrict__ x) {
    int b = blockIdx.x, t = threadIdx.x;
    int img = b / BPI;
    int w = t >> 5, lane = t & 31;

    __shared__ int sh[NWARPS * BINS];
#pragma unroll
    for (int i = t; i < NWARPS * BINS; i += 256) sh[i] = 0;

    float mn = fdec(g_minmax[img]);
    float mx = fdec(g_minmax[N_IMG + img]);
    float inv = 1.0f / (mx - mn + 1e-8f);        // exact div, once per thread
    __syncthreads();

    int base4 = b * (CHUNK / 4);
    uchar4* gi = reinterpret_cast<uchar4*>(g_idx);

#pragma unroll
    for (int i = 0; i < 8; i++) {
        float4 v = x[base4 + i * 256 + t];
        // norm = ((x - mn) * 255) * (1/denom); clip [0,255]; trunc
        int b0 = (int)fminf(fmaxf((v.x - mn) * 255.0f * inv, 0.0f), 255.0f);
        int b1 = (int)fminf(fmaxf((v.y - mn) * 255.0f * inv, 0.0f), 255.0f);
        int b2 = (int)fminf(fmaxf((v.z - mn) * 255.0f * inv, 0.0f), 255.0f);
        int b3 = (int)fminf(fmaxf((v.w - mn) * 255.0f * inv, 0.0f), 255.0f);
        gi[base4 + i * 256 + t] =
            make_uchar4((unsigned char)b0, (unsigned char)b1,
                        (unsigned char)b2, (unsigned char)b3);
        // warp-aggregated shared atomics (per-warp private hist)
        int bins[4] = {b0, b1, b2, b3};
#pragma unroll
        for (int j = 0; j < 4; j++) {
            unsigned m = __match_any_sync(0xffffffffu, bins[j]);
            if (lane == (__ffs(m) - 1))
                atomicAdd(&sh[w * BINS + bins[j]], __popc(m));
        }
    }
    __syncthreads();
    // merge 8 private hists -> global (one bin per thread, 256 == blockDim)
    int s = 0;
#pragma unroll
    for (int ww = 0; ww < NWARPS; ww++) s += sh[ww * BINS + t];
    if (s) atomicAdd(&g_hist[img * BINS + t], s);
}

// ---------------- k3: cumsum -> normalized LUT --------------------------------
__global__ void __launch_bounds__(256) k_cdf() {
    int img = blockIdx.x, t = threadIdx.x;
    int lane = t & 31, w = t >> 5;
    int v = g_hist[img * BINS + t];
    int s = v;
#pragma unroll
    for (int o = 1; o < 32; o <<= 1) {
        int n = __shfl_up_sync(0xffffffffu, s, o);
        if (lane >= o) s += n;
    }
    __shared__ int wsum[NWARPS], woff[NWARPS];
    if (lane == 31) wsum[w] = s;
    __syncthreads();
    if (t == 0) {
        int acc = 0;
#pragma unroll
        for (int i = 0; i < NWARPS; i++) { woff[i] = acc; acc += wsum[i]; }
    }
    __syncthreads();
    int cdf = s + woff[w];                       // inclusive scan, exact int
    __shared__ float sc0, stot;
    if (t == 0)   sc0  = (float)cdf;             // cdf.min() == cdf[0]
    if (t == 255) stot = (float)cdf;             // cdf.max() == cdf[255]
    __syncthreads();
    g_lut[img * BINS + t] = ((float)cdf - sc0) / (stot - sc0 + 1e-8f);
}

// ---------------- k4: gather LUT[idx] -----------------------------------------
__global__ void __launch_bounds__(256) k_gather(float4* __restrict__ out) {
    int b = blockIdx.x, t = threadIdx.x;
    int img = b / BPI;
    __shared__ float lut[BINS];
    lut[t] = g_lut[img * BINS + t];
    __syncthreads();
    int base4 = b * (CHUNK / 4);
    const uchar4* gi = reinterpret_cast<const uchar4*>(g_idx);
#pragma unroll
    for (int i = 0; i < 8; i++) {
        uchar4 u = gi[base4 + i * 256 + t];
        out[base4 + i * 256 + t] =
            make_float4(lut[u.x], lut[u.y], lut[u.z], lut[u.w]);
    }
}

// ---------------- launch -------------------------------------------------------
extern "C" void kernel_launch(void* const* d_in, const int* in_sizes, int n_in,
                              void* d_out, int out_size) {
    const float4* x = reinterpret_cast<const float4*>(d_in[0]);
    float4* out = reinterpret_cast<float4*>(d_out);

    k_init  <<<N_IMG, 256>>>();
    k_minmax<<<NBLOCKS, 256>>>(x);
    k_hist  <<<NBLOCKS, 256>>>(x);
    k_cdf   <<<N_IMG, 256>>>();
    k_gather<<<NBLOCKS, 256>>>(out);
}

// round 2
// speedup vs baseline: 2.4903x; 2.4903x over previous
#include <cuda_runtime.h>
#include <cuda_bf16.h>
#include <cstdint>

#define N_IMG 64
#define IMG_ELEMS (3 * 512 * 512)          // 786432
#define TOTAL_ELEMS (N_IMG * IMG_ELEMS)    // 50331648
#define BINS 256

// ---- minmax geometry ----
#define MM_THREADS 256
#define MM_CHUNK   16384
#define MM_BPI     (IMG_ELEMS / MM_CHUNK)        // 48
#define MM_BLOCKS  (TOTAL_ELEMS / MM_CHUNK)      // 3072
#define MM_ITERS   (MM_CHUNK / 4 / MM_THREADS)   // 16

// ---- hist geometry (per-thread private smem hist, u8 counts) ----
#define H_THREADS  192
#define H_CHUNK    24576                          // 128 elems/thread -> counts <= 128
#define H_BPI      (IMG_ELEMS / H_CHUNK)          // 32
#define H_BLOCKS   (TOTAL_ELEMS / H_CHUNK)        // 2048
#define H_ITERS    (H_CHUNK / 4 / H_THREADS)      // 32

// ---- gather geometry ----
#define G_THREADS  256
#define G_CHUNK    16384
#define G_BPI      (IMG_ELEMS / G_CHUNK)          // 48
#define G_BLOCKS   (TOTAL_ELEMS / G_CHUNK)        // 3072
#define G_ITERS    (G_CHUNK / 4 / G_THREADS)      // 16

// ---------------- device scratch ----------------------------------------------
__device__ unsigned char g_idx[TOTAL_ELEMS];          // 48 MB bucket indices
__device__ unsigned int  g_minmax[2 * N_IMG];
__device__ int           g_hist[N_IMG * BINS];
__device__ float         g_lut[N_IMG * BINS];

__device__ __forceinline__ unsigned fenc(float f) {
    unsigned u = __float_as_uint(f);
    return (u & 0x80000000u) ? ~u : (u | 0x80000000u);
}
__device__ __forceinline__ float fdec(unsigned u) {
    u = (u & 0x80000000u) ? (u ^ 0x80000000u) : ~u;
    return __uint_as_float(u);
}

// ---------------- k0: reset scratch -------------------------------------------
__global__ void k_init() {
    int gt = blockIdx.x * 256 + threadIdx.x;     // 64*256 = 16384 = N_IMG*BINS
    g_hist[gt] = 0;
    if (gt < N_IMG) {
        g_minmax[gt] = 0xFFFFFFFFu;
        g_minmax[N_IMG + gt] = 0u;
    }
}

// ---------------- k1: per-image min/max ---------------------------------------
__global__ void __launch_bounds__(MM_THREADS) k_minmax(const float4* __restrict__ x) {
    int b = blockIdx.x, t = threadIdx.x;
    int img = b / MM_BPI;
    int base4 = b * (MM_CHUNK / 4);
    float mn = 3.4e38f, mx = -3.4e38f;
#pragma unroll
    for (int i = 0; i < MM_ITERS; i++) {
        float4 v = x[base4 + i * MM_THREADS + t];
        mn = fminf(mn, fminf(fminf(v.x, v.y), fminf(v.z, v.w)));
        mx = fmaxf(mx, fmaxf(fmaxf(v.x, v.y), fmaxf(v.z, v.w)));
    }
#pragma unroll
    for (int o = 16; o > 0; o >>= 1) {
        mn = fminf(mn, __shfl_xor_sync(0xffffffffu, mn, o));
        mx = fmaxf(mx, __shfl_xor_sync(0xffffffffu, mx, o));
    }
    __shared__ float smn[MM_THREADS / 32], smx[MM_THREADS / 32];
    int w = t >> 5;
    if ((t & 31) == 0) { smn[w] = mn; smx[w] = mx; }
    __syncthreads();
    if (t == 0) {
#pragma unroll
        for (int i = 1; i < MM_THREADS / 32; i++) {
            mn = fminf(mn, smn[i]);
            mx = fmaxf(mx, smx[i]);
        }
        atomicMin(&g_minmax[img], fenc(mn));
        atomicMax(&g_minmax[N_IMG + img], fenc(mx));
    }
}

// ---------------- k2: per-thread private hist (NO atomics) + idx write --------
__global__ void __launch_bounds__(H_THREADS) k_hist(const float4* __restrict__ x) {
    __shared__ unsigned char sh[H_THREADS * BINS];      // 48 KB, one 256B region/thread
    uint32_t* shw = reinterpret_cast<uint32_t*>(sh);

    int b = blockIdx.x, t = threadIdx.x;
    int img = b / H_BPI;
    unsigned lane = t & 31u;

    for (int i = t; i < H_THREADS * BINS / 4; i += H_THREADS) shw[i] = 0;

    float mn = fdec(g_minmax[img]);
    float mx = fdec(g_minmax[N_IMG + img]);
    float inv = 1.0f / (mx - mn + 1e-8f);
    __syncthreads();

    int base4 = b * (H_CHUNK / 4);
    uchar4* gi = reinterpret_cast<uchar4*>(g_idx);
    unsigned tbase = (unsigned)t * 256u;                 // byte base of my region

#pragma unroll 8
    for (int i = 0; i < H_ITERS; i++) {
        float4 v = x[base4 + i * H_THREADS + t];
        int b0 = (int)fminf(fmaxf((v.x - mn) * 255.0f * inv, 0.0f), 255.0f);
        int b1 = (int)fminf(fmaxf((v.y - mn) * 255.0f * inv, 0.0f), 255.0f);
        int b2 = (int)fminf(fmaxf((v.z - mn) * 255.0f * inv, 0.0f), 255.0f);
        int b3 = (int)fminf(fmaxf((v.w - mn) * 255.0f * inv, 0.0f), 255.0f);
        gi[base4 + i * H_THREADS + t] =
            make_uchar4((unsigned char)b0, (unsigned char)b1,
                        (unsigned char)b2, (unsigned char)b3);
        int bins[4] = {b0, b1, b2, b3};
#pragma unroll
        for (int j = 0; j < 4; j++) {
            unsigned bb = (unsigned)bins[j];
            // lane-rotated word layout: identical bins across lanes -> distinct banks
            unsigned w = ((bb >> 2) + lane) & 63u;
            sh[tbase + w * 4u + (bb & 3u)]++;            // private: no atomic needed
        }
    }
    __syncthreads();

    // Reduce: thread (q = t&63, c = t>>6) sums quad q over regions [c*64, c*64+64)
    int q = t & 63, c = t >> 6;
    uint32_t s02 = 0, s13 = 0;                           // packed u16 pairs
#pragma unroll 16
    for (int rr = 0; rr < 64; rr++) {
        int r = c * 64 + rr;
        unsigned w = ((unsigned)q + (unsigned)(r & 31)) & 63u;
        uint32_t v = shw[r * 64 + w];
        s02 += v & 0x00FF00FFu;                          // bins 4q+0 (lo16), 4q+2 (hi16)
        s13 += (v >> 8) & 0x00FF00FFu;                   // bins 4q+1 (lo16), 4q+3 (hi16)
    }
    __syncthreads();
    shw[t * 2] = s02;
    shw[t * 2 + 1] = s13;
    __syncthreads();
    if (t < 64) {
        uint32_t a02 = shw[t * 2]     + shw[(64 + t) * 2]     + shw[(128 + t) * 2];
        uint32_t a13 = shw[t * 2 + 1] + shw[(64 + t) * 2 + 1] + shw[(128 + t) * 2 + 1];
        // max 3 * 16320 < 65536: no cross-half carry
        int base = img * BINS + t * 4;
        atomicAdd(&g_hist[base + 0], (int)(a02 & 0xFFFFu));
        atomicAdd(&g_hist[base + 1], (int)(a13 & 0xFFFFu));
        atomicAdd(&g_hist[base + 2], (int)(a02 >> 16));
        atomicAdd(&g_hist[base + 3], (int)(a13 >> 16));
    }
}

// ---------------- k3: cumsum -> normalized LUT --------------------------------
__global__ void __launch_bounds__(256) k_cdf() {
    int img = blockIdx.x, t = threadIdx.x;
    int lane = t & 31, w = t >> 5;
    int v = g_hist[img * BINS + t];
    int s = v;
#pragma unroll
    for (int o = 1; o < 32; o <<= 1) {
        int n = __shfl_up_sync(0xffffffffu, s, o);
        if (lane >= o) s += n;
    }
    __shared__ int wsum[8], woff[8];
    if (lane == 31) wsum[w] = s;
    __syncthreads();
    if (t == 0) {
        int acc = 0;
#pragma unroll
        for (int i = 0; i < 8; i++) { woff[i] = acc; acc += wsum[i]; }
    }
    __syncthreads();
    int cdf = s + woff[w];                       // inclusive scan, exact int
    __shared__ float sc0, stot;
    if (t == 0)   sc0  = (float)cdf;
    if (t == 255) stot = (float)cdf;
    __syncthreads();
    g_lut[img * BINS + t] = ((float)cdf - sc0) / (stot - sc0 + 1e-8f);
}

// ---------------- k4: gather LUT[idx] -----------------------------------------
__global__ void __launch_bounds__(G_THREADS) k_gather(float4* __restrict__ out) {
    int b = blockIdx.x, t = threadIdx.x;
    int img = b / G_BPI;
    __shared__ float lut[BINS];
    lut[t] = g_lut[img * BINS + t];
    __syncthreads();
    int base4 = b * (G_CHUNK / 4);
    const uchar4* gi = reinterpret_cast<const uchar4*>(g_idx);
#pragma unroll 8
    for (int i = 0; i < G_ITERS; i++) {
        uchar4 u = gi[base4 + i * G_THREADS + t];
        out[base4 + i * G_THREADS + t] =
            make_float4(lut[u.x], lut[u.y], lut[u.z], lut[u.w]);
    }
}

// ---------------- launch -------------------------------------------------------
extern "C" void kernel_launch(void* const* d_in, const int* in_sizes, int n_in,
                              void* d_out, int out_size) {
    const float4* x = reinterpret_cast<const float4*>(d_in[0]);
    float4* out = reinterpret_cast<float4*>(d_out);

    k_init  <<<N_IMG, 256>>>();
    k_minmax<<<MM_BLOCKS, MM_THREADS>>>(x);
    k_hist  <<<H_BLOCKS, H_THREADS>>>(x);
    k_cdf   <<<N_IMG, 256>>>();
    k_gather<<<G_BLOCKS, G_THREADS>>>(out);
}

// round 3
// speedup vs baseline: 2.6413x; 1.0606x over previous
#include <cuda_runtime.h>
#include <cuda_bf16.h>
#include <cstdint>

#define N_IMG 64
#define IMG_ELEMS (3 * 512 * 512)          // 786432
#define TOTAL_ELEMS (N_IMG * IMG_ELEMS)    // 50331648
#define BINS 256

// ---- minmax geometry ----
#define MM_THREADS 256
#define MM_CHUNK   16384
#define MM_BPI     (IMG_ELEMS / MM_CHUNK)        // 48
#define MM_BLOCKS  (TOTAL_ELEMS / MM_CHUNK)      // 3072
#define MM_ITERS   (MM_CHUNK / 4 / MM_THREADS)   // 16

// ---- hist geometry (per-thread private smem hist, u8, bank == lane) ----
#define H_THREADS  192                            // 6 warps
#define H_CHUNK    24576                          // 128 elems/thread -> u8 counts safe
#define H_BPI      (IMG_ELEMS / H_CHUNK)          // 32
#define H_BLOCKS   (TOTAL_ELEMS / H_CHUNK)        // 2048
#define H_ITERS    (H_CHUNK / 4 / H_THREADS)      // 32
#define H_WORDS    (H_THREADS * BINS / 4)         // 12288 u32 words = 48 KB

// ---- gather geometry ----
#define G_THREADS  256
#define G_CHUNK    16384
#define G_BPI      (IMG_ELEMS / G_CHUNK)          // 48
#define G_BLOCKS   (TOTAL_ELEMS / G_CHUNK)        // 3072
#define G_ITERS    (G_CHUNK / 4 / G_THREADS)      // 16

// ---------------- device scratch ----------------------------------------------
__device__ unsigned char g_idx[TOTAL_ELEMS];          // 48 MB bucket indices
__device__ unsigned int  g_minmax[2 * N_IMG];
__device__ int           g_hist[N_IMG * BINS];

__device__ __forceinline__ unsigned fenc(float f) {
    unsigned u = __float_as_uint(f);
    return (u & 0x80000000u) ? ~u : (u | 0x80000000u);
}
__device__ __forceinline__ float fdec(unsigned u) {
    u = (u & 0x80000000u) ? (u ^ 0x80000000u) : ~u;
    return __uint_as_float(u);
}

// ---------------- k0: reset scratch -------------------------------------------
__global__ void k_init() {
    int gt = blockIdx.x * 256 + threadIdx.x;     // 64*256 = 16384 = N_IMG*BINS
    g_hist[gt] = 0;
    if (gt < N_IMG) {
        g_minmax[gt] = 0xFFFFFFFFu;
        g_minmax[N_IMG + gt] = 0u;
    }
}

// ---------------- k1: per-image min/max ---------------------------------------
__global__ void __launch_bounds__(MM_THREADS) k_minmax(const float4* __restrict__ x) {
    int b = blockIdx.x, t = threadIdx.x;
    int img = b / MM_BPI;
    int base4 = b * (MM_CHUNK / 4);
    float mn = 3.4e38f, mx = -3.4e38f;
#pragma unroll
    for (int i = 0; i < MM_ITERS; i++) {
        float4 v = x[base4 + i * MM_THREADS + t];
        mn = fminf(mn, fminf(fminf(v.x, v.y), fminf(v.z, v.w)));
        mx = fmaxf(mx, fmaxf(fmaxf(v.x, v.y), fmaxf(v.z, v.w)));
    }
#pragma unroll
    for (int o = 16; o > 0; o >>= 1) {
        mn = fminf(mn, __shfl_xor_sync(0xffffffffu, mn, o));
        mx = fmaxf(mx, __shfl_xor_sync(0xffffffffu, mx, o));
    }
    __shared__ float smn[MM_THREADS / 32], smx[MM_THREADS / 32];
    int w = t >> 5;
    if ((t & 31) == 0) { smn[w] = mn; smx[w] = mx; }
    __syncthreads();
    if (t == 0) {
#pragma unroll
        for (int i = 1; i < MM_THREADS / 32; i++) {
            mn = fminf(mn, smn[i]);
            mx = fmaxf(mx, smx[i]);
        }
        atomicMin(&g_minmax[img], fenc(mn));
        atomicMax(&g_minmax[N_IMG + img], fenc(mx));
    }
}

// ---------------- k2: per-thread private hist, bank == lane (ZERO conflicts) --
// Counter byte addr for (thread t, bin b):
//   word = (t>>5)*2048 + (b>>2)*32 + (t&31);  byte = b&3
// => bank = (t&31) regardless of bin: every LDS/STS is 32 distinct banks.
__global__ void __launch_bounds__(H_THREADS) k_hist(const float4* __restrict__ x) {
    __shared__ uint32_t shw[H_WORDS];                    // 48 KB
    unsigned char* sh = reinterpret_cast<unsigned char*>(shw);

    int b = blockIdx.x, t = threadIdx.x;
    int img = b / H_BPI;
    unsigned lane = t & 31u;
    unsigned wreg = (unsigned)(t >> 5);                  // warp id 0..5

    // vector zero: 12288 words = 3072 uint4
    uint4* shv = reinterpret_cast<uint4*>(shw);
#pragma unroll
    for (int i = 0; i < H_WORDS / 4 / H_THREADS; i++)
        shv[t + i * H_THREADS] = make_uint4(0, 0, 0, 0);

    float mn = fdec(g_minmax[img]);
    float mx = fdec(g_minmax[N_IMG + img]);
    float inv = 1.0f / (mx - mn + 1e-8f);
    __syncthreads();

    int base4 = b * (H_CHUNK / 4);
    uchar4* gi = reinterpret_cast<uchar4*>(g_idx);
    // byte base of this thread's column: region + lane slot
    unsigned cbase = wreg * 8192u + lane * 4u;

#pragma unroll 8
    for (int i = 0; i < H_ITERS; i++) {
        float4 v = x[base4 + i * H_THREADS + t];
        unsigned b0 = (unsigned)(int)fminf(fmaxf((v.x - mn) * 255.0f * inv, 0.0f), 255.0f);
        unsigned b1 = (unsigned)(int)fminf(fmaxf((v.y - mn) * 255.0f * inv, 0.0f), 255.0f);
        unsigned b2 = (unsigned)(int)fminf(fmaxf((v.z - mn) * 255.0f * inv, 0.0f), 255.0f);
        unsigned b3 = (unsigned)(int)fminf(fmaxf((v.w - mn) * 255.0f * inv, 0.0f), 255.0f);
        gi[base4 + i * H_THREADS + t] =
            make_uchar4((unsigned char)b0, (unsigned char)b1,
                        (unsigned char)b2, (unsigned char)b3);
        sh[cbase + (b0 >> 2) * 128u + (b0 & 3u)]++;
        sh[cbase + (b1 >> 2) * 128u + (b1 & 3u)]++;
        sh[cbase + (b2 >> 2) * 128u + (b2 & 3u)]++;
        sh[cbase + (b3 >> 2) * 128u + (b3 & 3u)]++;
    }
    __syncthreads();

    // Reduce: thread (q = t&63, g = t>>6) sums quad q over warp-regions {2g, 2g+1}
    // lane-staggered ((i+t)&31) -> distinct banks across a warp every iteration.
    int q = t & 63, g = t >> 6;
    uint32_t s02 = 0, s13 = 0;                           // packed u16 pairs
#pragma unroll
    for (int r = 0; r < 2; r++) {
        int w2 = g * 2 + r;
#pragma unroll 8
        for (int i = 0; i < 32; i++) {
            int l = (i + t) & 31;
            uint32_t v = shw[w2 * 2048 + q * 32 + l];
            s02 += v & 0x00FF00FFu;                      // bins 4q+0 / 4q+2
            s13 += (v >> 8) & 0x00FF00FFu;               // bins 4q+1 / 4q+3
        }
    }
    __syncthreads();
    shw[t * 2] = s02;
    shw[t * 2 + 1] = s13;
    __syncthreads();
    if (t < 64) {
        uint32_t a02 = shw[t * 2]     + shw[(64 + t) * 2]     + shw[(128 + t) * 2];
        uint32_t a13 = shw[t * 2 + 1] + shw[(64 + t) * 2 + 1] + shw[(128 + t) * 2 + 1];
        // max 24576 per half: no cross-half carry
        int base = img * BINS + t * 4;
        atomicAdd(&g_hist[base + 0], (int)(a02 & 0xFFFFu));
        atomicAdd(&g_hist[base + 1], (int)(a13 & 0xFFFFu));
        atomicAdd(&g_hist[base + 2], (int)(a02 >> 16));
        atomicAdd(&g_hist[base + 3], (int)(a13 >> 16));
    }
}

// ---------------- k3: cdf scan (per block) + gather LUT[idx] ------------------
__global__ void __launch_bounds__(G_THREADS) k_gather(float4* __restrict__ out) {
    int b = blockIdx.x, t = threadIdx.x;
    int img = b / G_BPI;
    __shared__ float lut[BINS];
    {
        int lane = t & 31, w = t >> 5;
        int s = g_hist[img * BINS + t];
#pragma unroll
        for (int o = 1; o < 32; o <<= 1) {
            int n = __shfl_up_sync(0xffffffffu, s, o);
            if (lane >= o) s += n;
        }
        __shared__ int wsum[8], woff[8];
        if (lane == 31) wsum[w] = s;
        __syncthreads();
        if (t == 0) {
            int acc = 0;
#pragma unroll
            for (int i = 0; i < 8; i++) { woff[i] = acc; acc += wsum[i]; }
        }
        __syncthreads();
        int cdf = s + woff[w];                   // inclusive scan, exact int
        __shared__ float sc0, stot;
        if (t == 0)   sc0  = (float)cdf;
        if (t == 255) stot = (float)cdf;
        __syncthreads();
        lut[t] = ((float)cdf - sc0) / (stot - sc0 + 1e-8f);
        __syncthreads();
    }
    int base4 = b * (G_CHUNK / 4);
    const uchar4* gi = reinterpret_cast<const uchar4*>(g_idx);
#pragma unroll 8
    for (int i = 0; i < G_ITERS; i++) {
        uchar4 u = gi[base4 + i * G_THREADS + t];
        out[base4 + i * G_THREADS + t] =
            make_float4(lut[u.x], lut[u.y], lut[u.z], lut[u.w]);
    }
}

// ---------------- launch -------------------------------------------------------
extern "C" void kernel_launch(void* const* d_in, const int* in_sizes, int n_in,
                              void* d_out, int out_size) {
    const float4* x = reinterpret_cast<const float4*>(d_in[0]);
    float4* out = reinterpret_cast<float4*>(d_out);

    k_init  <<<N_IMG, 256>>>();
    k_minmax<<<MM_BLOCKS, MM_THREADS>>>(x);
    k_hist  <<<H_BLOCKS, H_THREADS>>>(x);
    k_gather<<<G_BLOCKS, G_THREADS>>>(out);
}

// round 4
// speedup vs baseline: 2.6733x; 1.0121x over previous
#include <cuda_runtime.h>
#include <cuda_bf16.h>
#include <cstdint>

#define N_IMG 64
#define IMG_ELEMS (3 * 512 * 512)          // 786432
#define TOTAL_ELEMS (N_IMG * IMG_ELEMS)    // 50331648
#define BINS 256

// ---- minmax geometry ----
#define MM_THREADS 256
#define MM_CHUNK   16384
#define MM_BPI     (IMG_ELEMS / MM_CHUNK)        // 48
#define MM_BLOCKS  (TOTAL_ELEMS / MM_CHUNK)      // 3072
#define MM_ITERS   (MM_CHUNK / 4 / MM_THREADS)   // 16

// ---- hist geometry (per-thread private smem hist, u8, bank == lane) ----
#define H_THREADS  192                            // 6 warps
#define H_CHUNK    24576                          // 128 elems/thread -> u8 counts safe
#define H_BPI      (IMG_ELEMS / H_CHUNK)          // 32
#define H_BLOCKS   (TOTAL_ELEMS / H_CHUNK)        // 2048
#define H_ITERS    (H_CHUNK / 4 / H_THREADS)      // 32
#define H_WORDS    (H_THREADS * BINS / 4)         // 12288 u32 words = 48 KB

// ---- gather geometry ----
#define G_THREADS  256
#define G_CHUNK    16384
#define G_BPI      (IMG_ELEMS / G_CHUNK)          // 48
#define G_BLOCKS   (TOTAL_ELEMS / G_CHUNK)        // 3072
#define G_ITERS    (G_CHUNK / 4 / G_THREADS)      // 16

// ---------------- device scratch ----------------------------------------------
__device__ unsigned char g_idx[TOTAL_ELEMS];          // 48 MB bucket indices
__device__ unsigned int  g_minmax[2 * N_IMG];
__device__ int           g_hist[N_IMG * BINS];

__device__ __forceinline__ unsigned fenc(float f) {
    unsigned u = __float_as_uint(f);
    return (u & 0x80000000u) ? ~u : (u | 0x80000000u);
}
__device__ __forceinline__ float fdec(unsigned u) {
    u = (u & 0x80000000u) ? (u ^ 0x80000000u) : ~u;
    return __uint_as_float(u);
}

// ---------------- k0: reset scratch -------------------------------------------
__global__ void k_init() {
    int gt = blockIdx.x * 256 + threadIdx.x;     // 64*256 = 16384 = N_IMG*BINS
    g_hist[gt] = 0;
    if (gt < N_IMG) {
        g_minmax[gt] = 0xFFFFFFFFu;
        g_minmax[N_IMG + gt] = 0u;
    }
}

// ---------------- k1: per-image min/max ---------------------------------------
__global__ void __launch_bounds__(MM_THREADS) k_minmax(const float4* __restrict__ x) {
    int b = blockIdx.x, t = threadIdx.x;
    int img = b / MM_BPI;
    int base4 = b * (MM_CHUNK / 4);
    float mn = 3.4e38f, mx = -3.4e38f;
#pragma unroll
    for (int i = 0; i < MM_ITERS; i++) {
        float4 v = x[base4 + i * MM_THREADS + t];
        mn = fminf(mn, fminf(fminf(v.x, v.y), fminf(v.z, v.w)));
        mx = fmaxf(mx, fmaxf(fmaxf(v.x, v.y), fmaxf(v.z, v.w)));
    }
#pragma unroll
    for (int o = 16; o > 0; o >>= 1) {
        mn = fminf(mn, __shfl_xor_sync(0xffffffffu, mn, o));
        mx = fmaxf(mx, __shfl_xor_sync(0xffffffffu, mx, o));
    }
    __shared__ float smn[MM_THREADS / 32], smx[MM_THREADS / 32];
    int w = t >> 5;
    if ((t & 31) == 0) { smn[w] = mn; smx[w] = mx; }
    __syncthreads();
    if (t == 0) {
#pragma unroll
        for (int i = 1; i < MM_THREADS / 32; i++) {
            mn = fminf(mn, smn[i]);
            mx = fmaxf(mx, smx[i]);
        }
        atomicMin(&g_minmax[img], fenc(mn));
        atomicMax(&g_minmax[N_IMG + img], fenc(mx));
    }
}

// ---------------- k2: per-thread private hist, bank == lane (ZERO conflicts) --
__global__ void __launch_bounds__(H_THREADS) k_hist(const float4* __restrict__ x) {
    __shared__ uint32_t shw[H_WORDS];                    // 48 KB
    unsigned char* sh = reinterpret_cast<unsigned char*>(shw);

    int b = blockIdx.x, t = threadIdx.x;
    int img = b / H_BPI;
    unsigned lane = t & 31u;
    unsigned wreg = (unsigned)(t >> 5);                  // warp id 0..5

    uint4* shv = reinterpret_cast<uint4*>(shw);
#pragma unroll
    for (int i = 0; i < H_WORDS / 4 / H_THREADS; i++)
        shv[t + i * H_THREADS] = make_uint4(0, 0, 0, 0);

    float mn = fdec(g_minmax[img]);
    float mx = fdec(g_minmax[N_IMG + img]);
    float inv = 1.0f / (mx - mn + 1e-8f);
    __syncthreads();

    int base4 = b * (H_CHUNK / 4);
    uchar4* gi = reinterpret_cast<uchar4*>(g_idx);
    unsigned cbase = wreg * 8192u + lane * 4u;           // bank == lane column

#pragma unroll 8
    for (int i = 0; i < H_ITERS; i++) {
        // x is on its last read: evict-first so L2 keeps g_idx resident
        float4 v = __ldcs(&x[base4 + i * H_THREADS + t]);
        unsigned b0 = (unsigned)(int)fminf(fmaxf((v.x - mn) * 255.0f * inv, 0.0f), 255.0f);
        unsigned b1 = (unsigned)(int)fminf(fmaxf((v.y - mn) * 255.0f * inv, 0.0f), 255.0f);
        unsigned b2 = (unsigned)(int)fminf(fmaxf((v.z - mn) * 255.0f * inv, 0.0f), 255.0f);
        unsigned b3 = (unsigned)(int)fminf(fmaxf((v.w - mn) * 255.0f * inv, 0.0f), 255.0f);
        gi[base4 + i * H_THREADS + t] =
            make_uchar4((unsigned char)b0, (unsigned char)b1,
                        (unsigned char)b2, (unsigned char)b3);
        sh[cbase + (b0 >> 2) * 128u + (b0 & 3u)]++;
        sh[cbase + (b1 >> 2) * 128u + (b1 & 3u)]++;
        sh[cbase + (b2 >> 2) * 128u + (b2 & 3u)]++;
        sh[cbase + (b3 >> 2) * 128u + (b3 & 3u)]++;
    }
    __syncthreads();

    // Reduce: thread (q = t&63, g = t>>6) sums quad q over warp-regions {2g, 2g+1}
    int q = t & 63, g = t >> 6;
    uint32_t s02 = 0, s13 = 0;                           // packed u16 pairs
#pragma unroll
    for (int r = 0; r < 2; r++) {
        int w2 = g * 2 + r;
#pragma unroll 8
        for (int i = 0; i < 32; i++) {
            int l = (i + t) & 31;
            uint32_t v = shw[w2 * 2048 + q * 32 + l];
            s02 += v & 0x00FF00FFu;
            s13 += (v >> 8) & 0x00FF00FFu;
        }
    }
    __syncthreads();
    shw[t * 2] = s02;
    shw[t * 2 + 1] = s13;
    __syncthreads();
    if (t < 64) {
        uint32_t a02 = shw[t * 2]     + shw[(64 + t) * 2]     + shw[(128 + t) * 2];
        uint32_t a13 = shw[t * 2 + 1] + shw[(64 + t) * 2 + 1] + shw[(128 + t) * 2 + 1];
        int base = img * BINS + t * 4;
        atomicAdd(&g_hist[base + 0], (int)(a02 & 0xFFFFu));
        atomicAdd(&g_hist[base + 1], (int)(a13 & 0xFFFFu));
        atomicAdd(&g_hist[base + 2], (int)(a02 >> 16));
        atomicAdd(&g_hist[base + 3], (int)(a13 >> 16));
    }
}

// ---------------- k3: cdf scan + gather, replicated LUT (bank == lane) --------
__global__ void __launch_bounds__(G_THREADS) k_gather(float4* __restrict__ out) {
    int b = blockIdx.x, t = threadIdx.x;
    int img = b / G_BPI;
    unsigned lane = t & 31u;
    __shared__ float lutw[BINS * 32];                    // 32 KB: word = bin*32 + lane
    {
        int w = t >> 5;
        int s = g_hist[img * BINS + t];
#pragma unroll
        for (int o = 1; o < 32; o <<= 1) {
            int n = __shfl_up_sync(0xffffffffu, s, (unsigned)o);
            if ((int)lane >= o) s += n;
        }
        __shared__ int wsum[8], woff[8];
        if (lane == 31) wsum[w] = s;
        __syncthreads();
        if (t == 0) {
            int acc = 0;
#pragma unroll
            for (int i = 0; i < 8; i++) { woff[i] = acc; acc += wsum[i]; }
        }
        __syncthreads();
        int cdf = s + woff[w];                   // inclusive scan, exact int
        __shared__ float sc0, stot;
        if (t == 0)   sc0  = (float)cdf;
        if (t == 255) stot = (float)cdf;
        __syncthreads();
        float val = ((float)cdf - sc0) / (stot - sc0 + 1e-8f);
        // replicate: thread t owns bin t; staggered stores, bank = (l+lane)&31
#pragma unroll
        for (int l = 0; l < 32; l++)
            lutw[t * 32 + ((l + lane) & 31u)] = val;
        __syncthreads();
    }
    int base4 = b * (G_CHUNK / 4);
    const uchar4* gi = reinterpret_cast<const uchar4*>(g_idx);
#pragma unroll 8
    for (int i = 0; i < G_ITERS; i++) {
        uchar4 u = gi[base4 + i * G_THREADS + t];
        float4 o4 = make_float4(lutw[u.x * 32u + lane], lutw[u.y * 32u + lane],
                                lutw[u.z * 32u + lane], lutw[u.w * 32u + lane]);
        // out is write-once streaming: evict-first, keep g_idx in L2
        __stcs(&out[base4 + i * G_THREADS + t], o4);
    }
}

// ---------------- launch -------------------------------------------------------
extern "C" void kernel_launch(void* const* d_in, const int* in_sizes, int n_in,
                              void* d_out, int out_size) {
    const float4* x = reinterpret_cast<const float4*>(d_in[0]);
    float4* out = reinterpret_cast<float4*>(d_out);

    k_init  <<<N_IMG, 256>>>();
    k_minmax<<<MM_BLOCKS, MM_THREADS>>>(x);
    k_hist  <<<H_BLOCKS, H_THREADS>>>(x);
    k_gather<<<G_BLOCKS, G_THREADS>>>(out);
}